// round 9
// baseline (speedup 1.0000x reference)
#include <cuda_runtime.h>
#include <cuda_fp16.h>
#include <cstdint>

// SGC_63677185130849: N=100000 nodes, E=1600000 edges, D=50, C=47, K=2 hops.
#define MAX_N 100000
#define MAX_E 1600000
#define MAX_EPAD (MAX_E + 4 * MAX_N)   // padded CSR capacity
#define D_FEAT 50
#define N_CLS 47
#define HCHUNKS 25                  // 50 real halves = 25 half2
#define ROW_HALVES 64               // padded to 128 bytes
#define ROW_BYTES 128
#define SCAN_B 1024
#define MAX_SB 128

// Scratch (device globals — allocations forbidden)
__device__ __align__(16) __half g_ha[MAX_N * ROW_HALVES];   // 12.8 MB
__device__ __align__(16) __half g_hb[MAX_N * ROW_HALVES];   // 12.8 MB
__device__ float  g_dinv[MAX_N];
__device__ int    g_cnt[MAX_N];
__device__ int    g_scan[MAX_N];
__device__ int    g_bsum[MAX_SB];
__device__ int    g_off[MAX_N + 1];   // padded CSR offsets
__device__ int    g_cur[MAX_N];
__device__ int2   g_cedge[MAX_EPAD];  // {src_byte_off(128B rows), f32bits(dinv[src])}

// ---- packed fp32x2 FMA (Blackwell FFMA2; PTX-only) ----
__device__ __forceinline__ void fma_f32x2(float2& d, float2 a, float2 b) {
    asm("fma.rn.f32x2 %0, %1, %2, %0;"
        : "+l"(*reinterpret_cast<unsigned long long*>(&d))
        : "l"(*reinterpret_cast<unsigned long long*>(&a)),
          "l"(*reinterpret_cast<unsigned long long*>(&b)));
}

// ---------------- degree count + feat fp32 -> padded fp16 (fused) ----------------
// Grid must cover max(E, N*32).

__global__ void k_count_conv(const int* __restrict__ dst, const float* __restrict__ feat,
                             int E, int N) {
    int i = blockIdx.x * blockDim.x + threadIdx.x;
    if (i < E) atomicAdd(&g_cnt[dst[i]], 1);
    int total = N * 32;                       // half2 slots in padded matrix
    if (i < total) {
        int row = i >> 5;
        int c = i & 31;
        float2 v = make_float2(0.f, 0.f);
        if (c < HCHUNKS) v = reinterpret_cast<const float2*>(feat)[row * HCHUNKS + c];
        reinterpret_cast<__half2*>(g_ha)[i] = __float22half2_rn(v);
    }
}

// -------- scan over PADDED counts (deg rounded up to multiple of 4) --------

__global__ void k_scan1(int N) {
    __shared__ int ws[32];
    int t = threadIdx.x;
    int i = blockIdx.x * SCAN_B + t;
    int v = (i < N) ? g_cnt[i] : 0;
    if (i < N) g_dinv[i] = rsqrtf(1.0f + (float)v);
    int x = (v + 3) & ~3;                    // padded count
    #pragma unroll
    for (int o = 1; o < 32; o <<= 1) {
        int y = __shfl_up_sync(0xffffffffu, x, o);
        if ((t & 31) >= o) x += y;
    }
    if ((t & 31) == 31) ws[t >> 5] = x;
    __syncthreads();
    if (t < 32) {
        int y = ws[t];
        #pragma unroll
        for (int o = 1; o < 32; o <<= 1) {
            int z = __shfl_up_sync(0xffffffffu, y, o);
            if (t >= o) y += z;
        }
        ws[t] = y;
    }
    __syncthreads();
    int incl = x + ((t >= 32) ? ws[(t >> 5) - 1] : 0);
    if (i < N) g_scan[i] = incl;
    if (t == SCAN_B - 1) g_bsum[blockIdx.x] = incl;
}

__global__ void k_scan2(int NB) {
    __shared__ int s[MAX_SB];
    int t = threadIdx.x;
    int v = (t < NB) ? g_bsum[t] : 0;
    s[t] = v;
    __syncthreads();
    for (int o = 1; o < MAX_SB; o <<= 1) {
        int x = (t >= o) ? s[t - o] : 0;
        __syncthreads();
        s[t] += x;
        __syncthreads();
    }
    if (t < NB) g_bsum[t] = s[t];
}

__global__ void k_scan3(int N, int NB) {
    int i = blockIdx.x * blockDim.x + threadIdx.x;
    if (i > N) return;
    int excl;
    if (i == 0) excl = 0;
    else if (i == N) excl = g_bsum[NB - 1];   // padded total
    else {
        int j = i - 1;
        int b = j / SCAN_B;
        excl = g_scan[j] + (b > 0 ? g_bsum[b - 1] : 0);
    }
    g_off[i] = excl;
    if (i < N) g_cur[i] = excl;
}

// ---------------- CSR scatter: {src byte offset, dinv[src]} ----------------

__global__ void k_scatter(const int* __restrict__ src, const int* __restrict__ dst, int E) {
    int i = blockIdx.x * blockDim.x + threadIdx.x;
    if (i < E) {
        int s = src[i];
        int d = dst[i];
        int p = atomicAdd(&g_cur[d], 1);
        g_cedge[p] = make_int2(s * ROW_BYTES, __float_as_int(g_dinv[s]));
    }
}

// Fill pad slots (up to 3 per node) with {row 0, weight 0}.
__global__ void k_padfill(int N) {
    int i = blockIdx.x * blockDim.x + threadIdx.x;
    if (i < N) {
        int p = g_cur[i];
        int e = g_off[i + 1];
        for (; p < e; p++) g_cedge[p] = make_int2(0, 0);
    }
}

// ---------------- propagation: warp-per-node, 4 edges per iteration ----------------
// Lane 8g+l handles bytes [16l,16l+16) of edge (k+g)'s row via one warp-wide
// LDG.128 (512B per issue). Cross-group shfl_xor reduction at the end.
// hout[n] = dinv_n * ( dinv_n * hin[n] + sum_e dinv_src * hin[src] )

__global__ void __launch_bounds__(256) k_gather(const __half* __restrict__ hin,
                                                __half* __restrict__ hout, int N) {
    int n = (blockIdx.x * blockDim.x + threadIdx.x) >> 5;
    int lane = threadIdx.x & 31;
    if (n >= N) return;

    int g = lane >> 3;                 // edge group 0..3
    int l = lane & 7;                  // 16B chunk 0..7

    int base = g_off[n];
    int end  = g_off[n + 1];
    float dv = g_dinv[n];

    const char* hb = reinterpret_cast<const char*>(hin) + 16 * l;

    float2 a0, a1, a2, a3;
    {
        // self term: only group 0 contributes (others would quadruple it)
        uint4 rv = *reinterpret_cast<const uint4*>(hb + n * ROW_BYTES);
        float sw = (g == 0) ? dv : 0.f;
        float2 f;
        f = __half22float2(*reinterpret_cast<const __half2*>(&rv.x)); a0 = make_float2(sw * f.x, sw * f.y);
        f = __half22float2(*reinterpret_cast<const __half2*>(&rv.y)); a1 = make_float2(sw * f.x, sw * f.y);
        f = __half22float2(*reinterpret_cast<const __half2*>(&rv.z)); a2 = make_float2(sw * f.x, sw * f.y);
        f = __half22float2(*reinterpret_cast<const __half2*>(&rv.w)); a3 = make_float2(sw * f.x, sw * f.y);
    }

    const int2* ep = g_cedge + base + g;
    #pragma unroll 2
    for (int k = base; k < end; k += 4, ep += 4) {
        int2 pe = *ep;                                  // group-uniform record
        float2 w2 = make_float2(__int_as_float(pe.y), __int_as_float(pe.y));
        uint4 rv = *reinterpret_cast<const uint4*>(hb + pe.x);
        fma_f32x2(a0, __half22float2(*reinterpret_cast<const __half2*>(&rv.x)), w2);
        fma_f32x2(a1, __half22float2(*reinterpret_cast<const __half2*>(&rv.y)), w2);
        fma_f32x2(a2, __half22float2(*reinterpret_cast<const __half2*>(&rv.z)), w2);
        fma_f32x2(a3, __half22float2(*reinterpret_cast<const __half2*>(&rv.w)), w2);
    }

    // reduce across the 4 groups (lanes xor 8, xor 16)
    #pragma unroll
    for (int o = 8; o <= 16; o <<= 1) {
        a0.x += __shfl_xor_sync(0xffffffffu, a0.x, o);
        a0.y += __shfl_xor_sync(0xffffffffu, a0.y, o);
        a1.x += __shfl_xor_sync(0xffffffffu, a1.x, o);
        a1.y += __shfl_xor_sync(0xffffffffu, a1.y, o);
        a2.x += __shfl_xor_sync(0xffffffffu, a2.x, o);
        a2.y += __shfl_xor_sync(0xffffffffu, a2.y, o);
        a3.x += __shfl_xor_sync(0xffffffffu, a3.x, o);
        a3.y += __shfl_xor_sync(0xffffffffu, a3.y, o);
    }

    if (lane < 8) {
        __half2 h0 = __float22half2_rn(make_float2(dv * a0.x, dv * a0.y));
        __half2 h1 = __float22half2_rn(make_float2(dv * a1.x, dv * a1.y));
        __half2 h2 = __float22half2_rn(make_float2(dv * a2.x, dv * a2.y));
        __half2 h3 = __float22half2_rn(make_float2(dv * a3.x, dv * a3.y));
        uint4 o4;
        o4.x = *reinterpret_cast<uint32_t*>(&h0);
        o4.y = *reinterpret_cast<uint32_t*>(&h1);
        o4.z = *reinterpret_cast<uint32_t*>(&h2);
        o4.w = *reinterpret_cast<uint32_t*>(&h3);
        *reinterpret_cast<uint4*>(
            reinterpret_cast<char*>(hout) + n * ROW_BYTES + 16 * l) = o4;
    }
}

// ---------------- projection out = h @ W^T + b ----------------

#define GEMM_NODES 128

__global__ void __launch_bounds__(GEMM_NODES) k_gemm(const __half* __restrict__ h,
                                                     const float* __restrict__ W,
                                                     const float* __restrict__ b,
                                                     float* __restrict__ out, int N) {
    __shared__ float2 Ws2[N_CLS * HCHUNKS];                       // 9400 B
    __shared__ float bs[N_CLS];
    __shared__ __align__(16) char buf[HCHUNKS * GEMM_NODES * 8];  // 25600 B (union)
    float2* ht2 = reinterpret_cast<float2*>(buf);                 // [25][128]
    float*  ot  = reinterpret_cast<float*>(buf);                  // [128*47] (reuse)

    int tid = threadIdx.x;
    for (int i = tid; i < N_CLS * HCHUNKS; i += GEMM_NODES)
        Ws2[i] = reinterpret_cast<const float2*>(W)[i];
    if (tid < N_CLS) bs[tid] = b[tid];

    int n0 = blockIdx.x * GEMM_NODES;
    int nodes = min(GEMM_NODES, N - n0);

    for (int i = tid; i < nodes * HCHUNKS; i += GEMM_NODES) {
        int nl = i / HCHUNKS;
        int c = i - nl * HCHUNKS;
        __half2 v = *reinterpret_cast<const __half2*>(
            reinterpret_cast<const char*>(h) + (size_t)(n0 + nl) * ROW_BYTES + 4 * c);
        ht2[c * GEMM_NODES + nl] = __half22float2(v);
    }
    __syncthreads();

    float2 row[HCHUNKS];
    if (tid < nodes) {
        #pragma unroll
        for (int c = 0; c < HCHUNKS; c++) row[c] = ht2[c * GEMM_NODES + tid];
    }
    __syncthreads();    // ht2 dead; buf becomes ot

    if (tid < nodes) {
        #pragma unroll 1
        for (int cc = 0; cc < N_CLS; cc++) {
            float2 a = make_float2(bs[cc], 0.f);
            const float2* wr = &Ws2[cc * HCHUNKS];
            #pragma unroll
            for (int c = 0; c < HCHUNKS; c++) fma_f32x2(a, row[c], wr[c]);
            ot[tid * N_CLS + cc] = a.x + a.y;
        }
    }
    __syncthreads();

    for (int i = tid; i < nodes * N_CLS; i += GEMM_NODES)
        out[(size_t)n0 * N_CLS + i] = ot[i];
}

// ---------------- launch ----------------

extern "C" void kernel_launch(void* const* d_in, const int* in_sizes, int n_in,
                              void* d_out, int out_size) {
    const float* feat = (const float*)d_in[0];
    const float* W    = (const float*)d_in[1];
    const float* b    = (const float*)d_in[2];
    const int* esrc   = (const int*)d_in[3];
    const int* edst   = (const int*)d_in[4];
    // d_in[5] = K (device scalar); hops statically unrolled to 2.

    int C = in_sizes[2];
    int D = in_sizes[1] / C;
    int N = in_sizes[0] / D;
    int E = in_sizes[3];

    __half* ha; cudaGetSymbolAddress((void**)&ha, g_ha);
    __half* hb; cudaGetSymbolAddress((void**)&hb, g_hb);
    int* cnt;   cudaGetSymbolAddress((void**)&cnt, g_cnt);

    const int T = 256;
    int NB = (N + SCAN_B - 1) / SCAN_B;

    cudaMemsetAsync(cnt, 0, (size_t)N * sizeof(int));
    int conv_work = N * 32;
    int fused_work = (E > conv_work) ? E : conv_work;
    k_count_conv<<<(fused_work + T - 1) / T, T>>>(edst, feat, E, N);
    k_scan1<<<NB, SCAN_B>>>(N);
    k_scan2<<<1, MAX_SB>>>(NB);
    k_scan3<<<(N + 1 + T - 1) / T, T>>>(N, NB);
    k_scatter<<<(E + T - 1) / T, T>>>(esrc, edst, E);
    k_padfill<<<(N + T - 1) / T, T>>>(N);

    int gblocks = (N * 32 + T - 1) / T;
    k_gather<<<gblocks, T>>>(ha, hb, N);
    k_gather<<<gblocks, T>>>(hb, ha, N);

    k_gemm<<<(N + GEMM_NODES - 1) / GEMM_NODES, GEMM_NODES>>>(ha, W, b, (float*)d_out, N);
}

// round 10
// speedup vs baseline: 1.4155x; 1.4155x over previous
#include <cuda_runtime.h>
#include <cuda_fp16.h>
#include <cstdint>

// SGC_63677185130849: N=100000 nodes, E=1600000 edges, D=50, C=47, K=2 hops.
#define MAX_N 100000
#define MAX_E 1600000
#define D_FEAT 50
#define N_CLS 47
#define HCHUNKS 25                  // 50 real halves = 25 half2
#define ROW_HALVES 64               // padded to 128 bytes
#define ROW_BYTES 128
#define SCAN_B 1024
#define MAX_SB 128

// Scratch (device globals — allocations forbidden)
__device__ __align__(16) __half g_ha[MAX_N * ROW_HALVES];   // 12.8 MB
__device__ __align__(16) __half g_hb[MAX_N * ROW_HALVES];   // 12.8 MB
__device__ float  g_dinv[MAX_N];
__device__ int    g_cnt[MAX_N];
__device__ int    g_scan[MAX_N];
__device__ int    g_bsum[MAX_SB];
__device__ int    g_off[MAX_N + 1];
__device__ int    g_cur[MAX_N];
__device__ int2   g_cedge[MAX_E];   // {src_byte_off(128B rows), f32bits(dinv[src])}

// ---- packed fp32x2 FMA (Blackwell FFMA2; PTX-only) ----
__device__ __forceinline__ void fma_f32x2(float2& d, float2 a, float2 b) {
    asm("fma.rn.f32x2 %0, %1, %2, %0;"
        : "+l"(*reinterpret_cast<unsigned long long*>(&d))
        : "l"(*reinterpret_cast<unsigned long long*>(&a)),
          "l"(*reinterpret_cast<unsigned long long*>(&b)));
}

// ---------------- degree count + feat fp32 -> padded fp16 (fused) ----------------
// Grid must cover max(E, N*32).

__global__ void k_count_conv(const int* __restrict__ dst, const float* __restrict__ feat,
                             int E, int N) {
    int i = blockIdx.x * blockDim.x + threadIdx.x;
    if (i < E) atomicAdd(&g_cnt[dst[i]], 1);
    int total = N * 32;                       // half2 slots in padded matrix
    if (i < total) {
        int row = i >> 5;
        int c = i & 31;
        float2 v = make_float2(0.f, 0.f);
        if (c < HCHUNKS) v = reinterpret_cast<const float2*>(feat)[row * HCHUNKS + c];
        reinterpret_cast<__half2*>(g_ha)[i] = __float22half2_rn(v);
    }
}

// ---------------- scan (3 kernels); scan1 also computes dinv ----------------

__global__ void k_scan1(int N) {
    __shared__ int ws[32];
    int t = threadIdx.x;
    int i = blockIdx.x * SCAN_B + t;
    int v = (i < N) ? g_cnt[i] : 0;
    if (i < N) g_dinv[i] = rsqrtf(1.0f + (float)v);
    int x = v;
    #pragma unroll
    for (int o = 1; o < 32; o <<= 1) {
        int y = __shfl_up_sync(0xffffffffu, x, o);
        if ((t & 31) >= o) x += y;
    }
    if ((t & 31) == 31) ws[t >> 5] = x;
    __syncthreads();
    if (t < 32) {
        int y = ws[t];
        #pragma unroll
        for (int o = 1; o < 32; o <<= 1) {
            int z = __shfl_up_sync(0xffffffffu, y, o);
            if (t >= o) y += z;
        }
        ws[t] = y;
    }
    __syncthreads();
    int incl = x + ((t >= 32) ? ws[(t >> 5) - 1] : 0);
    if (i < N) g_scan[i] = incl;
    if (t == SCAN_B - 1) g_bsum[blockIdx.x] = incl;
}

__global__ void k_scan2(int NB) {
    __shared__ int s[MAX_SB];
    int t = threadIdx.x;
    int v = (t < NB) ? g_bsum[t] : 0;
    s[t] = v;
    __syncthreads();
    for (int o = 1; o < MAX_SB; o <<= 1) {
        int x = (t >= o) ? s[t - o] : 0;
        __syncthreads();
        s[t] += x;
        __syncthreads();
    }
    if (t < NB) g_bsum[t] = s[t];
}

__global__ void k_scan3(int N, int E) {
    int i = blockIdx.x * blockDim.x + threadIdx.x;
    if (i > N) return;
    int excl;
    if (i == 0) excl = 0;
    else if (i == N) excl = E;
    else {
        int j = i - 1;
        int b = j / SCAN_B;
        excl = g_scan[j] + (b > 0 ? g_bsum[b - 1] : 0);
    }
    g_off[i] = excl;
    if (i < N) g_cur[i] = excl;
}

// ---------------- CSR scatter: {src byte offset, dinv[src]} ----------------

__global__ void k_scatter(const int* __restrict__ src, const int* __restrict__ dst, int E) {
    int i = blockIdx.x * blockDim.x + threadIdx.x;
    if (i < E) {
        int s = src[i];
        int d = dst[i];
        int p = atomicAdd(&g_cur[d], 1);
        g_cedge[p] = make_int2(s * ROW_BYTES, __float_as_int(g_dinv[s]));
    }
}

// ---------------- propagation: warp-per-node gather ----------------
// hout[n] = dinv_n * ( dinv_n * hin[n] + sum_e dinv_src * hin[src] )
// Edge record fetched warp-uniformly (broadcast); all 32 lanes carry one
// aligned half2 of the 128B row (lanes 25..31 are zero padding).
// unroll 8: front-batch 8 record loads then 8 independent row loads -> MLP ~8.

__global__ void __launch_bounds__(256) k_gather(const __half* __restrict__ hin,
                                                __half* __restrict__ hout, int N) {
    int n = (blockIdx.x * blockDim.x + threadIdx.x) >> 5;
    int lane = threadIdx.x & 31;
    if (n >= N) return;

    int base = g_off[n];
    int end  = g_off[n + 1];
    float dv = g_dinv[n];

    const char* hb = reinterpret_cast<const char*>(hin) + 4 * lane;

    float2 acc;
    {
        float2 f = __half22float2(*reinterpret_cast<const __half2*>(hb + n * ROW_BYTES));
        acc.x = dv * f.x;
        acc.y = dv * f.y;
    }

    #pragma unroll 8
    for (int k = base; k < end; k++) {
        int2 pe = g_cedge[k];                 // warp-uniform broadcast load
        float ww = __int_as_float(pe.y);
        float2 f = __half22float2(*reinterpret_cast<const __half2*>(hb + pe.x));
        acc.x = fmaf(ww, f.x, acc.x);
        acc.y = fmaf(ww, f.y, acc.y);
    }

    acc.x *= dv;
    acc.y *= dv;
    *reinterpret_cast<__half2*>(
        reinterpret_cast<char*>(hout) + n * ROW_BYTES + 4 * lane) =
        __float22half2_rn(acc);
}

// ---------------- projection out = h @ W^T + b ----------------

#define GEMM_NODES 128

__global__ void __launch_bounds__(GEMM_NODES) k_gemm(const __half* __restrict__ h,
                                                     const float* __restrict__ W,
                                                     const float* __restrict__ b,
                                                     float* __restrict__ out, int N) {
    __shared__ float2 Ws2[N_CLS * HCHUNKS];                       // 9400 B
    __shared__ float bs[N_CLS];
    __shared__ __align__(16) char buf[HCHUNKS * GEMM_NODES * 8];  // 25600 B (union)
    float2* ht2 = reinterpret_cast<float2*>(buf);                 // [25][128]
    float*  ot  = reinterpret_cast<float*>(buf);                  // [128*47] (reuse)

    int tid = threadIdx.x;
    for (int i = tid; i < N_CLS * HCHUNKS; i += GEMM_NODES)
        Ws2[i] = reinterpret_cast<const float2*>(W)[i];
    if (tid < N_CLS) bs[tid] = b[tid];

    int n0 = blockIdx.x * GEMM_NODES;
    int nodes = min(GEMM_NODES, N - n0);

    for (int i = tid; i < nodes * HCHUNKS; i += GEMM_NODES) {
        int nl = i / HCHUNKS;
        int c = i - nl * HCHUNKS;
        __half2 v = *reinterpret_cast<const __half2*>(
            reinterpret_cast<const char*>(h) + (size_t)(n0 + nl) * ROW_BYTES + 4 * c);
        ht2[c * GEMM_NODES + nl] = __half22float2(v);
    }
    __syncthreads();

    float2 row[HCHUNKS];
    if (tid < nodes) {
        #pragma unroll
        for (int c = 0; c < HCHUNKS; c++) row[c] = ht2[c * GEMM_NODES + tid];
    }
    __syncthreads();    // ht2 dead; buf becomes ot

    if (tid < nodes) {
        #pragma unroll 1
        for (int cc = 0; cc < N_CLS; cc++) {
            float2 a = make_float2(bs[cc], 0.f);
            const float2* wr = &Ws2[cc * HCHUNKS];
            #pragma unroll
            for (int c = 0; c < HCHUNKS; c++) fma_f32x2(a, row[c], wr[c]);
            ot[tid * N_CLS + cc] = a.x + a.y;
        }
    }
    __syncthreads();

    for (int i = tid; i < nodes * N_CLS; i += GEMM_NODES)
        out[(size_t)n0 * N_CLS + i] = ot[i];
}

// ---------------- launch ----------------

extern "C" void kernel_launch(void* const* d_in, const int* in_sizes, int n_in,
                              void* d_out, int out_size) {
    const float* feat = (const float*)d_in[0];
    const float* W    = (const float*)d_in[1];
    const float* b    = (const float*)d_in[2];
    const int* esrc   = (const int*)d_in[3];
    const int* edst   = (const int*)d_in[4];
    // d_in[5] = K (device scalar); hops statically unrolled to 2.

    int C = in_sizes[2];
    int D = in_sizes[1] / C;
    int N = in_sizes[0] / D;
    int E = in_sizes[3];

    __half* ha; cudaGetSymbolAddress((void**)&ha, g_ha);
    __half* hb; cudaGetSymbolAddress((void**)&hb, g_hb);
    int* cnt;   cudaGetSymbolAddress((void**)&cnt, g_cnt);

    const int T = 256;
    int NB = (N + SCAN_B - 1) / SCAN_B;

    cudaMemsetAsync(cnt, 0, (size_t)N * sizeof(int));
    int conv_work = N * 32;
    int fused_work = (E > conv_work) ? E : conv_work;
    k_count_conv<<<(fused_work + T - 1) / T, T>>>(edst, feat, E, N);
    k_scan1<<<NB, SCAN_B>>>(N);
    k_scan2<<<1, MAX_SB>>>(NB);
    k_scan3<<<(N + 1 + T - 1) / T, T>>>(N, E);
    k_scatter<<<(E + T - 1) / T, T>>>(esrc, edst, E);

    int gblocks = (N * 32 + T - 1) / T;
    k_gather<<<gblocks, T>>>(ha, hb, N);
    k_gather<<<gblocks, T>>>(hb, ha, N);

    k_gemm<<<(N + GEMM_NODES - 1) / GEMM_NODES, GEMM_NODES>>>(ha, W, b, (float*)d_out, N);
}